// round 8
// baseline (speedup 1.0000x reference)
#include <cuda_runtime.h>
#include <cuda_bf16.h>
#include <cstdint>
#include <cstddef>

typedef unsigned long long ull;

#define TSTEPS 1024
#define GDIM   1024
#define HSEQ   ((size_t)TSTEPS * 256 * 256)

__device__ float g_xpb[(size_t)TSTEPS * 256 * GDIM];   // x@W_ih + bias

__device__ __forceinline__ float f2tf(float x) {
    uint32_t r; asm("cvt.rna.tf32.f32 %0, %1;" : "=r"(r) : "f"(x));
    return __uint_as_float(r);
}
__device__ __forceinline__ uint32_t sptr(const void* p) {
    return (uint32_t)__cvta_generic_to_shared(p);
}
__device__ __forceinline__ void ldsm4(uint32_t a[4], uint32_t addr) {
    asm volatile("ldmatrix.sync.aligned.m8n8.x4.shared.b16 {%0,%1,%2,%3}, [%4];"
        : "=r"(a[0]), "=r"(a[1]), "=r"(a[2]), "=r"(a[3]) : "r"(addr));
}
__device__ __forceinline__ void mma8(float c[4], const uint32_t a[4], uint32_t b0, uint32_t b1) {
    asm volatile("mma.sync.aligned.m16n8k8.row.col.f32.tf32.tf32.f32 "
        "{%0,%1,%2,%3}, {%4,%5,%6,%7}, {%8,%9}, {%0,%1,%2,%3};"
        : "+f"(c[0]), "+f"(c[1]), "+f"(c[2]), "+f"(c[3])
        : "r"(a[0]), "r"(a[1]), "r"(a[2]), "r"(a[3]), "r"(b0), "r"(b1));
}
__device__ __forceinline__ float sigf(float x) { return 1.f / (1.f + __expf(-x)); }
__device__ __forceinline__ uint32_t mapa_rank(uint32_t addr, uint32_t rank) {
    uint32_t r;
    asm("mapa.shared::cluster.u32 %0, %1, %2;" : "=r"(r) : "r"(addr), "r"(rank));
    return r;
}
__device__ __forceinline__ void mbar_init(uint32_t a, uint32_t cnt) {
    asm volatile("mbarrier.init.shared.b64 [%0], %1;" :: "r"(a), "r"(cnt) : "memory");
}
__device__ __forceinline__ void mbar_expect(uint32_t a, uint32_t bytes) {
    asm volatile("mbarrier.arrive.expect_tx.shared.b64 _, [%0], %1;" :: "r"(a), "r"(bytes) : "memory");
}
__device__ __forceinline__ void mbar_wait(uint32_t a, uint32_t parity) {
    asm volatile(
        "{\n\t.reg .pred P;\n\t"
        "WL_%=:\n\t"
        "mbarrier.try_wait.parity.acquire.cta.shared::cta.b64 P, [%0], %1, 0x989680;\n\t"
        "@P bra.uni WD_%=;\n\t"
        "bra.uni WL_%=;\n\t"
        "WD_%=:\n\t}"
        :: "r"(a), "r"(parity) : "memory");
}
__device__ __forceinline__ void bulk_s2s(uint32_t dst, uint32_t src, uint32_t bytes, uint32_t mbar) {
    asm volatile("cp.async.bulk.shared::cluster.shared::cta.mbarrier::complete_tx::bytes "
                 "[%0], [%1], %2, [%3];"
        :: "r"(dst), "r"(src), "r"(bytes), "r"(mbar) : "memory");
}

// ============================================================================
// Projection (R7 version, 128x128 tiles — measured ~0.9ms, keep)
// ============================================================================
#define PASTR 68
#define PBSTR 136
#define PROJ_SMEM ((128 * PASTR + 64 * PBSTR) * 4)

__global__ void __launch_bounds__(256) proj_kernel(const float* __restrict__ X,
                                                   const float* __restrict__ W,
                                                   const float* __restrict__ bias) {
    extern __shared__ float sm[];
    float* As = sm;
    float* Bs = sm + 128 * PASTR;
    const int tid = threadIdx.x;
    const int nb = blockIdx.x * 128, mb = blockIdx.y * 128;
    const int w = tid >> 5, lane = tid & 31;
    const int g = lane >> 2, t4 = lane & 3;
    const int mw = w & 1, nw = w >> 1;

    float acc[4][4][4] = {};
    const uint32_t abase = sptr(As + (mw * 64 + (lane & 15)) * PASTR + (lane >> 4) * 4);

    for (int kc = 0; kc < 4; kc++) {
        if (kc) __syncthreads();
        #pragma unroll
        for (int i = 0; i < 8; i++) {
            int idx = tid + 256 * i, r = idx >> 4, c4 = idx & 15;
            float4 v = *(const float4*)(X + (size_t)(mb + r) * 256 + kc * 64 + c4 * 4);
            v.x = f2tf(v.x); v.y = f2tf(v.y); v.z = f2tf(v.z); v.w = f2tf(v.w);
            *(float4*)(As + r * PASTR + c4 * 4) = v;
        }
        #pragma unroll
        for (int i = 0; i < 8; i++) {
            int idx = tid + 256 * i, r = idx >> 5, c4 = idx & 31;
            float4 v = *(const float4*)(W + (size_t)(kc * 64 + r) * GDIM + nb + c4 * 4);
            v.x = f2tf(v.x); v.y = f2tf(v.y); v.z = f2tf(v.z); v.w = f2tf(v.w);
            *(float4*)(Bs + r * PBSTR + c4 * 4) = v;
        }
        __syncthreads();
        #pragma unroll
        for (int kt = 0; kt < 8; kt++) {
            uint32_t af[4][4];
            #pragma unroll
            for (int mt = 0; mt < 4; mt++)
                ldsm4(af[mt], abase + (uint32_t)(mt * 16 * PASTR * 4) + kt * 32);
            #pragma unroll
            for (int nt = 0; nt < 4; nt++) {
                int col = nw * 32 + nt * 8 + g;
                uint32_t b0 = __float_as_uint(Bs[(kt * 8 + t4) * PBSTR + col]);
                uint32_t b1 = __float_as_uint(Bs[(kt * 8 + t4 + 4) * PBSTR + col]);
                #pragma unroll
                for (int mt = 0; mt < 4; mt++) mma8(acc[mt][nt], af[mt], b0, b1);
            }
        }
    }
    #pragma unroll
    for (int mt = 0; mt < 4; mt++) {
        size_t r0 = (size_t)(mb + mw * 64 + mt * 16 + g);
        #pragma unroll
        for (int nt = 0; nt < 4; nt++) {
            int col = nb + nw * 32 + nt * 8 + 2 * t4;
            float b0 = __ldg(bias + col), b1 = __ldg(bias + col + 1);
            *(float2*)(g_xpb + r0 * GDIM + col) =
                make_float2(acc[mt][nt][0] + b0, acc[mt][nt][1] + b1);
            *(float2*)(g_xpb + (r0 + 8) * GDIM + col) =
                make_float2(acc[mt][nt][2] + b0, acc[mt][nt][3] + b1);
        }
    }
}

// ============================================================================
// Recurrence: 16 clusters x 8 CTAs (128 CTAs), ONE 16-row group per CTA.
// R6-style bulk DSMEM exchange (8 x 2KB, complete_tx), parity-doubled stage.
// SMEM floats: As[b] 2x4096 | gs 2112 | stage[p] 2x512 | 2 mbarriers
// ============================================================================
#define GSTR 132
#define AS_F(b)  ((b)*4096)
#define GS_F     8192
#define ST_F(p)  (10304 + (p)*512)
#define MB_BYTE  45312
#define LSMEM_BYTES 45344

__global__ void __launch_bounds__(256, 1) __cluster_dims__(8, 1, 1)
lstm_kernel(const float* __restrict__ Whh, float* __restrict__ out, int tail) {
    extern __shared__ float smem[];
    const uint32_t smem0 = sptr(smem);
    const int tid = threadIdx.x;
    const int w = tid >> 5, lane = tid & 31;
    const int g = lane >> 2, t4 = lane & 3;
    const int cid = blockIdx.x >> 3;          // 0..15, owns rows [16cid,16cid+16)
    uint32_t r; asm("mov.u32 %0, %%cluster_ctarank;" : "=r"(r));

    if (tid == 0) {
        mbar_init(smem0 + MB_BYTE, 1);
        mbar_init(smem0 + MB_BYTE + 8, 1);
        mbar_expect(smem0 + MB_BYTE, 16384);
        mbar_expect(smem0 + MB_BYTE + 8, 16384);
    }

    // W_hh slice as persistent mma B-fragments (gate-cols only; row-independent)
    uint32_t bf[32][2][2];
    #pragma unroll
    for (int kt = 0; kt < 32; kt++)
        #pragma unroll
        for (int nt = 0; nt < 2; nt++) {
            int l = w * 16 + nt * 8 + g;
            int gcol = (l >> 5) * 256 + (int)r * 32 + (l & 31);
            bf[kt][nt][0] = __float_as_uint(f2tf(Whh[(size_t)(kt * 8 + t4) * GDIM + gcol]));
            bf[kt][nt][1] = __float_as_uint(f2tf(Whh[(size_t)(kt * 8 + t4 + 4) * GDIM + gcol]));
        }
    __syncthreads();
    asm volatile("barrier.cluster.arrive.aligned;" ::: "memory");
    asm volatile("barrier.cluster.wait.aligned;" ::: "memory");

    // ldsm lane addressing on blocked+swizzled layout (verified R6 scheme)
    const int laneRow = lane & 15, cb = lane >> 4, rx = laneRow & 7;
    const uint32_t rowbase = (uint32_t)laneRow * 128;

    // pointwise / staging ownership
    const int prow = tid >> 4;          // 0..15
    const int pc = (tid & 15) * 2;      // 0..30
    const int schunk = (pc >> 2) ^ (prow & 7);
    const int stoff = prow * 32 + schunk * 4 + (pc & 3);
    float c0 = 0.f, c1 = 0.f;
    int ph[2] = {0, 0};

    for (int t = 0; t < TSTEPS; t++) {
        const int b = t & 1, nbuf = b ^ 1;
        // prefetch xp (overlaps wait + mma)
        const float* xr = g_xpb + (size_t)t * (256 * GDIM)
                        + (size_t)(cid * 16 + prow) * GDIM + r * 32 + pc;
        float2 x0 = __ldcg((const float2*)xr);
        float2 x1 = __ldcg((const float2*)(xr + 256));
        float2 x2 = __ldcg((const float2*)(xr + 512));
        float2 x3 = __ldcg((const float2*)(xr + 768));

        float acc[2][4] = {}, acc2[2][4] = {};
        if (t) {
            uint32_t mb = smem0 + MB_BYTE + b * 8;
            mbar_wait(mb, (uint32_t)ph[b]);
            ph[b] ^= 1;
            if (tid == 0) mbar_expect(mb, 16384);
            uint32_t ab = smem0 + AS_F(b) * 4 + rowbase;
            #pragma unroll
            for (int kt = 0; kt < 16; kt++) {
                uint32_t a[4];
                uint32_t c = (uint32_t)(((((kt & 3) << 1) | cb) ^ rx) << 4);
                ldsm4(a, ab + ((kt >> 2) << 11) + c);
                mma8(acc[0], a, bf[kt][0][0], bf[kt][0][1]);
                mma8(acc[1], a, bf[kt][1][0], bf[kt][1][1]);
            }
            #pragma unroll
            for (int kt = 16; kt < 32; kt++) {
                uint32_t a[4];
                uint32_t c = (uint32_t)(((((kt & 3) << 1) | cb) ^ rx) << 4);
                ldsm4(a, ab + ((kt >> 2) << 11) + c);
                mma8(acc2[0], a, bf[kt][0][0], bf[kt][0][1]);
                mma8(acc2[1], a, bf[kt][1][0], bf[kt][1][1]);
            }
        }
        // scatter gates
        float* gsp = smem + GS_F;
        #pragma unroll
        for (int nt = 0; nt < 2; nt++) {
            int lc = w * 16 + nt * 8 + 2 * t4;
            *(float2*)&gsp[g * GSTR + lc] =
                make_float2(acc[nt][0] + acc2[nt][0], acc[nt][1] + acc2[nt][1]);
            *(float2*)&gsp[(g + 8) * GSTR + lc] =
                make_float2(acc[nt][2] + acc2[nt][2], acc[nt][3] + acc2[nt][3]);
        }
        __syncthreads();
        // pointwise
        float2 vi = *(float2*)&gsp[prow * GSTR + pc];
        float2 vf = *(float2*)&gsp[prow * GSTR + 32 + pc];
        float2 vg = *(float2*)&gsp[prow * GSTR + 64 + pc];
        float2 vo = *(float2*)&gsp[prow * GSTR + 96 + pc];
        float i0 = sigf(vi.x + x0.x), i1 = sigf(vi.y + x0.y);
        float f0 = sigf(vf.x + x1.x), f1 = sigf(vf.y + x1.y);
        float G0 = tanhf(vg.x + x2.x), G1 = tanhf(vg.y + x2.y);
        float o0 = sigf(vo.x + x3.x), o1 = sigf(vo.y + x3.y);
        c0 = f0 * c0 + i0 * G0;
        c1 = f1 * c1 + i1 * G1;
        float h0 = o0 * tanhf(c0), h1 = o1 * tanhf(c1);
        // stage swizzled tf32 block (parity b) for the bulk push
        *(float2*)(smem + ST_F(b) + stoff) = make_float2(f2tf(h0), f2tf(h1));
        // stream h out
        size_t off = (size_t)(cid * 16 + prow) * 256 + r * 32 + pc;
        *(float2*)(out + (size_t)t * 65536 + off) = make_float2(h0, h1);
        if (tail && t == TSTEPS - 1) {
            *(float2*)(out + HSEQ + off) = make_float2(h0, h1);
            *(float2*)(out + HSEQ + 65536 + off) = make_float2(c0, c1);
        }
        __syncthreads();
        // async push: 8 x 2KB bulk copies with complete_tx at destinations
        if (tid == 0 && t < TSTEPS - 1) {
            asm volatile("fence.proxy.async.shared::cta;" ::: "memory");
            uint32_t src = smem0 + ST_F(b) * 4;
            uint32_t dstl = smem0 + AS_F(nbuf) * 4 + r * 2048;
            uint32_t mbl = smem0 + MB_BYTE + nbuf * 8;
            #pragma unroll
            for (uint32_t dr = 0; dr < 8; dr++)
                bulk_s2s(mapa_rank(dstl, dr), src, 2048u, mapa_rank(mbl, dr));
        }
    }
    if (tid == 0) {
        asm volatile("cp.async.bulk.commit_group;" ::: "memory");
        asm volatile("cp.async.bulk.wait_group.read 0;" ::: "memory");
    }
    __syncthreads();
    asm volatile("barrier.cluster.arrive.aligned;" ::: "memory");
    asm volatile("barrier.cluster.wait.aligned;" ::: "memory");
}

extern "C" void kernel_launch(void* const* d_in, const int* in_sizes, int n_in,
                              void* d_out, int out_size) {
    const float* x    = (const float*)d_in[0];
    const float* wih  = (const float*)d_in[1];
    const float* whh  = (const float*)d_in[2];
    const float* bias = (const float*)d_in[3];
    float* out = (float*)d_out;
    (void)in_sizes; (void)n_in;
    cudaFuncSetAttribute(proj_kernel, cudaFuncAttributeMaxDynamicSharedMemorySize, PROJ_SMEM);
    cudaFuncSetAttribute(lstm_kernel, cudaFuncAttributeMaxDynamicSharedMemorySize, LSMEM_BYTES);
    proj_kernel<<<dim3(8, 2048), 256, PROJ_SMEM>>>(x, wih, bias);
    int tail = ((size_t)out_size >= HSEQ + 2 * 65536) ? 1 : 0;
    lstm_kernel<<<128, 256, LSMEM_BYTES>>>(whh, out, tail);
}